// round 4
// baseline (speedup 1.0000x reference)
#include <cuda_runtime.h>
#include <cstdint>

// Problem constants
#define NPTS      65536      // 16*64*64 spatial positions
#define DIM       64
#define NCODE     1024
#define HW        4096       // 64*64
#define CHW       262144     // 64*64*64
#define TOTAL_Q   4194304    // 16*64*64*64

// Output layout (concatenated, reference return order, float32)
#define OFF_Q     0
#define OFF_LOSS  4194304
#define OFF_IDX   4194305
#define OFF_EMB   4259841
#define OFF_CS    4325377
#define OFF_EA    4326401

// Scratch (device globals; no allocation allowed)
__device__ float g_dw[DIM * NCODE];
__device__ float g_enc[NCODE];
__device__ float g_e2[NCODE];
__device__ float g_loss;

// Packed f32x2 FMA: d.lo += a.lo*b.lo ; d.hi += a.hi*b.hi  (2 FMAs / issue)
__device__ __forceinline__ void ffma2(unsigned long long& d,
                                      unsigned long long a,
                                      unsigned long long b) {
    asm("fma.rn.f32x2 %0, %1, %2, %0;" : "+l"(d) : "l"(a), "l"(b));
}
__device__ __forceinline__ float pair_sum(unsigned long long v) {
    float lo = __uint_as_float((unsigned)(v & 0xffffffffu));
    float hi = __uint_as_float((unsigned)(v >> 32));
    return lo + hi;
}

// ---------------------------------------------------------------------------
// Kernel 1: zero scratch + compute e2[k] = sum_d E[d][k]^2
// ---------------------------------------------------------------------------
__global__ void vq_init(const float* __restrict__ E) {
    int i = blockIdx.x * blockDim.x + threadIdx.x;
    if (i < DIM * NCODE) g_dw[i] = 0.0f;
    if (i < NCODE) {
        g_enc[i] = 0.0f;
        float s = 0.0f;
#pragma unroll
        for (int d = 0; d < DIM; ++d) {
            float v = E[d * NCODE + i];
            s = fmaf(v, v, s);
        }
        g_e2[i] = s;
    }
    if (i == 0) g_loss = 0.0f;
}

// ---------------------------------------------------------------------------
// Kernel 2: fused distance GEMM (f32x2 packed) + argmin + quantize + loss +
// EMA atomics.  Block: 256 threads, 128 points; 8 chunks of 128 codes.
// Channel dim packed into f32x2 lanes: smem tiles are [c/2][idx][{even,odd}].
// ---------------------------------------------------------------------------
__global__ void __launch_bounds__(256, 1)
vq_main(const float* __restrict__ x, const float* __restrict__ E,
        float* __restrict__ out) {
    extern __shared__ float sm[];
    float* x_p     = sm;                 // 8192 floats: [32 c2][128 m][2]
    float* e_p     = sm + 8192;          // 8192 floats: [32 c2][128 j][2] (swizzled)
    float* run_val = sm + 16384;         // [128]
    int*   run_idx = (int*)(sm + 16512); // [128]
    float* red     = sm + 16640;         // [256]

    const int tid = threadIdx.x;
    const int n0 = blockIdx.x * 128;
    const int bimg = n0 >> 12;           // n0 / 4096
    const int p0 = n0 & 4095;
    const float* xb = x + (size_t)bimg * CHW + p0;

    // ---- pack x tile: x_p[c2][m][par] = x[2*c2+par][m] for 128 points ----
#pragma unroll
    for (int r = 0; r < 4; ++r) {
        int g = tid + 256 * r;           // 0..1023
        int c2 = g >> 5;                 // 0..31
        int q = g & 31;                  // point group (4 points)
        float4 v0 = *(const float4*)(xb + (2 * c2) * HW + q * 4);
        float4 v1 = *(const float4*)(xb + (2 * c2 + 1) * HW + q * 4);
        float4 lo = make_float4(v0.x, v1.x, v0.y, v1.y);   // points 4q,4q+1
        float4 hi = make_float4(v0.z, v1.z, v0.w, v1.w);   // points 4q+2,4q+3
        *(float4*)(x_p + c2 * 256 + q * 8)     = lo;
        *(float4*)(x_p + c2 * 256 + q * 8 + 4) = hi;
    }
    if (tid < 128) {
        run_val[tid] = 3.4e38f;
        run_idx[tid] = 0;
    }

    const int tx = tid & 15;
    const int ty = tid >> 4;

    // b-side swizzled byte offsets within a c2 row (kills bank-quad conflicts)
    unsigned bo[4];
#pragma unroll
    for (int t = 0; t < 4; ++t)
        bo[t] = (unsigned)(((tx * 4 + t) * 16) ^ ((tx & 6) << 3));

    const ulonglong2* xp2 = (const ulonglong2*)x_p;
    const char* epc = (const char*)e_p;

    for (int chunk = 0; chunk < 8; ++chunk) {
        __syncthreads();  // x_p ready (first iter) / e_p reuse safe (later)
        // ---- pack E chunk into e_p with swizzle ----
#pragma unroll
        for (int r = 0; r < 4; ++r) {
            int g = tid + 256 * r;
            int c2 = g >> 5;
            int q = g & 31;              // code group (4 codes)
            const float* Eb = E + chunk * 128 + q * 4;
            float4 v0 = *(const float4*)(Eb + (2 * c2) * NCODE);
            float4 v1 = *(const float4*)(Eb + (2 * c2 + 1) * NCODE);
            float4 lo = make_float4(v0.x, v1.x, v0.y, v1.y);   // codes 4q,4q+1
            float4 hi = make_float4(v0.z, v1.z, v0.w, v1.w);   // codes 4q+2,4q+3
            unsigned c0 = (unsigned)(2 * q);       // chunk index in row
            unsigned o0 = (c0 * 16) ^ (((c0 >> 2) & 6) << 3);
            unsigned c1 = c0 + 1;
            unsigned o1 = (c1 * 16) ^ (((c1 >> 2) & 6) << 3);
            *(float4*)((char*)e_p + c2 * 1024 + o0) = lo;
            *(float4*)((char*)e_p + c2 * 1024 + o1) = hi;
        }
        __syncthreads();

        unsigned long long acc[8][8];
#pragma unroll
        for (int i = 0; i < 8; ++i)
#pragma unroll
            for (int j = 0; j < 8; ++j) acc[i][j] = 0ull;

#pragma unroll 4
        for (int c2 = 0; c2 < 32; ++c2) {
            // a: channel-pairs for points ty*8..ty*8+7 (broadcast across tx)
            ulonglong2 a0 = xp2[c2 * 64 + ty * 4 + 0];
            ulonglong2 a1 = xp2[c2 * 64 + ty * 4 + 1];
            ulonglong2 a2 = xp2[c2 * 64 + ty * 4 + 2];
            ulonglong2 a3 = xp2[c2 * 64 + ty * 4 + 3];
            unsigned long long A[8] = {a0.x, a0.y, a1.x, a1.y,
                                       a2.x, a2.y, a3.x, a3.y};
            // b: channel-pairs for codes tx*8..tx*8+7 (swizzled)
            const char* eb = epc + c2 * 1024;
            ulonglong2 b0 = *(const ulonglong2*)(eb + bo[0]);
            ulonglong2 b1 = *(const ulonglong2*)(eb + bo[1]);
            ulonglong2 b2 = *(const ulonglong2*)(eb + bo[2]);
            ulonglong2 b3 = *(const ulonglong2*)(eb + bo[3]);
            unsigned long long B[8] = {b0.x, b0.y, b1.x, b1.y,
                                       b2.x, b2.y, b3.x, b3.y};
#pragma unroll
            for (int i = 0; i < 8; ++i)
#pragma unroll
                for (int j = 0; j < 8; ++j)
                    ffma2(acc[i][j], A[i], B[j]);
        }

        // scores s = e2[k] - 2*dot; per-thread min, then reduce over tx lanes
        const int kbase = chunk * 128 + tx * 8;
        float e2v[8];
#pragma unroll
        for (int j = 0; j < 8; ++j) e2v[j] = g_e2[kbase + j];

#pragma unroll
        for (int i = 0; i < 8; ++i) {
            float bv = 3.4e38f;
            int bi = 0;
#pragma unroll
            for (int j = 0; j < 8; ++j) {
                float dot = pair_sum(acc[i][j]);
                float s = fmaf(-2.0f, dot, e2v[j]);
                if (s < bv) { bv = s; bi = kbase + j; }
            }
#pragma unroll
            for (int off = 8; off > 0; off >>= 1) {
                float ov = __shfl_xor_sync(0xffffffffu, bv, off);
                int   oi = __shfl_xor_sync(0xffffffffu, bi, off);
                if (ov < bv || (ov == bv && oi < bi)) { bv = ov; bi = oi; }
            }
            if (tx == 0) {
                int m = ty * 8 + i;
                if (bv < run_val[m]) { run_val[m] = bv; run_idx[m] = bi; }
            }
        }
    }
    __syncthreads();

    // ---- epilogue ----
    if (tid < 128) {
        int k = run_idx[tid];
        out[OFF_IDX + n0 + tid] = (float)k;
        atomicAdd(&g_enc[k], 1.0f);
    }

    float lsum = 0.0f;
    float* outq = out + OFF_Q + (size_t)bimg * CHW + p0;
#pragma unroll 4
    for (int r = 0; r < 32; ++r) {
        int e = tid + 256 * r;           // 0..8191
        int c = e >> 7;
        int m = e & 127;
        int k = run_idx[m];
        float xv = x_p[(c >> 1) * 256 + m * 2 + (c & 1)];
        float ev = E[c * NCODE + k];
        float diff = ev - xv;
        outq[c * HW + m] = xv + diff;    // mimic inputs + (quantized - inputs)
        lsum = fmaf(diff, diff, lsum);
        atomicAdd(&g_dw[c * NCODE + k], xv);
    }

    red[tid] = lsum;
    __syncthreads();
    for (int s = 128; s > 0; s >>= 1) {
        if (tid < s) red[tid] += red[tid + s];
        __syncthreads();
    }
    if (tid == 0) atomicAdd(&g_loss, red[0]);
}

// ---------------------------------------------------------------------------
// Kernel 3: EMA finalize + loss scalar
// ---------------------------------------------------------------------------
__global__ void vq_fin(const float* __restrict__ cs_in,
                       const float* __restrict__ ea_in,
                       float* __restrict__ out) {
    __shared__ float red[1024];
    int k = threadIdx.x;
    float ncs = cs_in[k] * 0.99f + 0.01f * g_enc[k];
    red[k] = ncs;
    __syncthreads();
    for (int s = 512; s > 0; s >>= 1) {
        if (k < s) red[k] += red[k + s];
        __syncthreads();
    }
    float n = red[0];
    out[OFF_CS + k] = ncs;
    float cs = (ncs + 1e-5f) / (n + 1024.0f * 1e-5f) * n;
#pragma unroll
    for (int d = 0; d < DIM; ++d) {
        int idx = d * NCODE + k;
        float nea = ea_in[idx] * 0.99f + 0.01f * g_dw[idx];
        out[OFF_EA + idx] = nea;
        out[OFF_EMB + idx] = nea / cs;
    }
    if (k == 0) out[OFF_LOSS] = 0.25f * g_loss * (1.0f / (float)TOTAL_Q);
}

// ---------------------------------------------------------------------------
extern "C" void kernel_launch(void* const* d_in, const int* in_sizes, int n_in,
                              void* d_out, int out_size) {
    const float* x  = (const float*)d_in[0];  // inputs [16,64,64,64]
    const float* E  = (const float*)d_in[1];  // embedding [64,1024]
    const float* cs = (const float*)d_in[2];  // cluster_size [1024]
    const float* ea = (const float*)d_in[3];  // embed_avg [64,1024]
    float* out = (float*)d_out;

    const int smem = 16896 * 4;  // 67584 bytes
    cudaFuncSetAttribute(vq_main, cudaFuncAttributeMaxDynamicSharedMemorySize, smem);

    vq_init<<<256, 256>>>(E);
    vq_main<<<NPTS / 128, 256, smem>>>(x, E, out);
    vq_fin<<<1, 1024>>>(cs, ea, out);
}

// round 6
// speedup vs baseline: 1.4097x; 1.4097x over previous
#include <cuda_runtime.h>
#include <cuda_bf16.h>
#include <cstdint>

// Problem constants
#define NPTS      65536
#define DIM       64
#define NCODE     1024
#define HW        4096
#define CHW       262144
#define TOTAL_Q   4194304

// Output layout (concatenated, reference return order, float32)
#define OFF_Q     0
#define OFF_LOSS  4194304
#define OFF_IDX   4194305
#define OFF_EMB   4259841
#define OFF_CS    4325377
#define OFF_EA    4326401

// Scratch
__device__ float g_dw[DIM * NCODE];
__device__ float g_enc[NCODE];
__device__ float g_e2[NCODE];
__device__ float g_loss;
__device__ int   g_nflag;
__device__ int   g_flagged[NPTS];

// ---------------- smem layout (bytes) ----------------
// A/B tiles: 128 rows x 272 bytes (64 bf16 hi @0, 64 bf16 lo @128, 16B pad)
#define ROWB     272
#define SM_A     0
#define SM_B     34816
#define SM_E2    69632          // 128 floats
#define SM_V1    70144          // 256 floats  (staging best  [row][half])
#define SM_V2    71168          // 256 floats  (staging 2nd)
#define SM_I1    72192          // 256 ints    (staging idx)
#define SM_RUNV  73216          // 128 floats
#define SM_RUNV2 73728          // 128 floats
#define SM_RUNI  74240          // 128 ints
#define SM_RED   74752          // 256 floats
#define SM_TOTAL 75776

__device__ __forceinline__ uint32_t smem_u32(const void* p) {
    uint32_t a;
    asm("{ .reg .u64 t; cvta.to.shared.u64 t, %1; cvt.u32.u64 %0, t; }" : "=r"(a) : "l"(p));
    return a;
}

#define LDSM4(r, a) \
    asm volatile("ldmatrix.sync.aligned.m8n8.x4.shared.b16 {%0,%1,%2,%3}, [%4];" \
        : "=r"((r)[0]), "=r"((r)[1]), "=r"((r)[2]), "=r"((r)[3]) : "r"(a))

#define MMA_BF16(d, a, b0, b1) \
    asm volatile("mma.sync.aligned.m16n8k16.row.col.f32.bf16.bf16.f32 " \
        "{%0,%1,%2,%3}, {%4,%5,%6,%7}, {%8,%9}, {%0,%1,%2,%3};" \
        : "+f"((d)[0]), "+f"((d)[1]), "+f"((d)[2]), "+f"((d)[3]) \
        : "r"((a)[0]), "r"((a)[1]), "r"((a)[2]), "r"((a)[3]), "r"(b0), "r"(b1))

__device__ __forceinline__ uint32_t pack_hilo(float v0, float v1, uint32_t& lo_pack) {
    __nv_bfloat16 h0 = __float2bfloat16(v0);
    __nv_bfloat16 h1 = __float2bfloat16(v1);
    __nv_bfloat16 l0 = __float2bfloat16(v0 - __bfloat162float(h0));
    __nv_bfloat16 l1 = __float2bfloat16(v1 - __bfloat162float(h1));
    uint32_t hp = ((uint32_t)__bfloat16_as_ushort(h1) << 16) | __bfloat16_as_ushort(h0);
    lo_pack    = ((uint32_t)__bfloat16_as_ushort(l1) << 16) | __bfloat16_as_ushort(l0);
    return hp;
}

// ---------------------------------------------------------------------------
// Kernel 1: init scratch + e2
// ---------------------------------------------------------------------------
__global__ void vq_init(const float* __restrict__ E) {
    int i = blockIdx.x * blockDim.x + threadIdx.x;
    if (i < DIM * NCODE) g_dw[i] = 0.0f;
    if (i < NCODE) {
        g_enc[i] = 0.0f;
        float s = 0.0f;
#pragma unroll
        for (int d = 0; d < DIM; ++d) {
            float v = E[d * NCODE + i];
            s = fmaf(v, v, s);
        }
        g_e2[i] = s;
    }
    if (i == 0) { g_loss = 0.0f; g_nflag = 0; }
}

// ---------------------------------------------------------------------------
// Kernel 2: bf16 mma.sync distance GEMM (hi/lo compensated) + argmin + epilogue
// 256 threads = 8 warps (4 M-groups x 2 N-groups), 128 points/CTA, 8 chunks.
// ---------------------------------------------------------------------------
__global__ void __launch_bounds__(256, 1)
vq_main(const float* __restrict__ x, const float* __restrict__ E,
        float* __restrict__ out) {
    extern __shared__ char sm[];
    const uint32_t sb = smem_u32(sm);
    float* e2s  = (float*)(sm + SM_E2);
    float* v1s  = (float*)(sm + SM_V1);
    float* v2s  = (float*)(sm + SM_V2);
    int*   i1s  = (int*)(sm + SM_I1);
    float* runv = (float*)(sm + SM_RUNV);
    float* runv2= (float*)(sm + SM_RUNV2);
    int*   runi = (int*)(sm + SM_RUNI);
    float* red  = (float*)(sm + SM_RED);

    const int tid  = threadIdx.x;
    const int wid  = tid >> 5;
    const int lane = tid & 31;
    const int n0   = blockIdx.x * 128;
    const int bimg = n0 >> 12;
    const int p0   = n0 & 4095;
    const float* xb = x + (size_t)bimg * CHW + p0;

    // ---- pack A tile: rows = points m, cols = 64 hi | 64 lo bf16 ----
#pragma unroll
    for (int it = 0; it < 16; ++it) {
        int g  = tid + 256 * it;          // 0..4095
        int c2 = g >> 7;                  // channel pair 0..31
        int m  = g & 127;
        float v0 = -2.0f * xb[(2 * c2) * HW + m];
        float v1 = -2.0f * xb[(2 * c2 + 1) * HW + m];
        uint32_t lp, hp = pack_hilo(v0, v1, lp);
        *(uint32_t*)(sm + SM_A + m * ROWB + c2 * 4)       = hp;
        *(uint32_t*)(sm + SM_A + m * ROWB + 128 + c2 * 4) = lp;
    }
    if (tid < 128) {
        runv[tid] = 3.4e38f; runv2[tid] = 3.4e38f; runi[tid] = 0;
    }

    // warp tile assignment
    const int wm  = wid >> 1;             // 0..3  -> M rows wm*32
    const int wn  = wid & 1;              // 0..1  -> N cols wn*64
    const int m0  = wm * 32;
    const int nb0 = wn * 64;
    // ldmatrix per-lane addressing
    const int mrow  = (lane & 7) + ((lane >> 3) & 1) * 8;   // row within 16-tile
    const int kcolB = ((lane >> 4) & 1) * 16;               // byte offset (col half)
    const uint32_t aBase = sb + SM_A + (m0 + mrow) * ROWB + kcolB;
    const uint32_t bBase = sb + SM_B + (nb0 + mrow) * ROWB + kcolB;

    for (int chunk = 0; chunk < 8; ++chunk) {
        __syncthreads();
        // ---- pack B (E chunk) ----
#pragma unroll
        for (int it = 0; it < 16; ++it) {
            int g  = tid + 256 * it;
            int c2 = g >> 7;
            int j  = g & 127;
            float v0 = E[(2 * c2) * NCODE + chunk * 128 + j];
            float v1 = E[(2 * c2 + 1) * NCODE + chunk * 128 + j];
            uint32_t lp, hp = pack_hilo(v0, v1, lp);
            *(uint32_t*)(sm + SM_B + j * ROWB + c2 * 4)       = hp;
            *(uint32_t*)(sm + SM_B + j * ROWB + 128 + c2 * 4) = lp;
        }
        if (tid < 128) e2s[tid] = g_e2[chunk * 128 + tid];
        __syncthreads();

        // ---- load A fragments (held all chunk) ----
        uint32_t Ahi[2][4][4], Alo[2][4][4];
#pragma unroll
        for (int mt = 0; mt < 2; ++mt)
#pragma unroll
            for (int kb = 0; kb < 4; ++kb) {
                LDSM4(Ahi[mt][kb], aBase + mt * (16 * ROWB) + kb * 32);
                LDSM4(Alo[mt][kb], aBase + mt * (16 * ROWB) + kb * 32 + 128);
            }

        float acc[2][8][4];
#pragma unroll
        for (int mt = 0; mt < 2; ++mt)
#pragma unroll
            for (int j = 0; j < 8; ++j)
#pragma unroll
                for (int c = 0; c < 4; ++c) acc[mt][j][c] = 0.0f;

        // ---- MMA mainloop ----
#pragma unroll
        for (int kb = 0; kb < 4; ++kb) {
#pragma unroll
            for (int nt = 0; nt < 4; ++nt) {
                uint32_t Bh[4];
                LDSM4(Bh, bBase + nt * (16 * ROWB) + kb * 32);
#pragma unroll
                for (int mt = 0; mt < 2; ++mt)
#pragma unroll
                    for (int h = 0; h < 2; ++h) {
                        MMA_BF16(acc[mt][nt * 2 + h], Ahi[mt][kb], Bh[h], Bh[h + 2]);
                        MMA_BF16(acc[mt][nt * 2 + h], Alo[mt][kb], Bh[h], Bh[h + 2]);
                    }
            }
#pragma unroll
            for (int nt = 0; nt < 4; ++nt) {
                uint32_t Bl[4];
                LDSM4(Bl, bBase + nt * (16 * ROWB) + kb * 32 + 128);
#pragma unroll
                for (int mt = 0; mt < 2; ++mt)
#pragma unroll
                    for (int h = 0; h < 2; ++h)
                        MMA_BF16(acc[mt][nt * 2 + h], Ahi[mt][kb], Bl[h], Bl[h + 2]);
            }
        }

        // ---- extraction: per-thread rows, then lane-group reduce ----
#pragma unroll
        for (int mt = 0; mt < 2; ++mt)
#pragma unroll
            for (int rr = 0; rr < 2; ++rr) {
                float b1v = 3.4e38f, b2v = 3.4e38f;
                int biI = 0;
#pragma unroll
                for (int j = 0; j < 8; ++j) {
                    int nA = nb0 + (j >> 1) * 16 + (j & 1) * 8 + (lane & 3) * 2;
                    float sc0 = acc[mt][j][rr * 2 + 0] + e2s[nA];
                    float sc1 = acc[mt][j][rr * 2 + 1] + e2s[nA + 1];
                    if (sc0 < b1v) { b2v = b1v; b1v = sc0; biI = chunk * 128 + nA; }
                    else if (sc0 < b2v) b2v = sc0;
                    if (sc1 < b1v) { b2v = b1v; b1v = sc1; biI = chunk * 128 + nA + 1; }
                    else if (sc1 < b2v) b2v = sc1;
                }
#pragma unroll
                for (int off = 1; off <= 2; off <<= 1) {
                    float o1 = __shfl_xor_sync(0xffffffffu, b1v, off);
                    float o2 = __shfl_xor_sync(0xffffffffu, b2v, off);
                    int   oi = __shfl_xor_sync(0xffffffffu, biI, off);
                    float nb2 = fminf(fminf(b2v, o2), fmaxf(b1v, o1));
                    if (o1 < b1v || (o1 == b1v && oi < biI)) { b1v = o1; biI = oi; }
                    b2v = nb2;
                }
                if ((lane & 3) == 0) {
                    int row = m0 + mt * 16 + (lane >> 2) + rr * 8;
                    v1s[row * 2 + wn] = b1v;
                    v2s[row * 2 + wn] = b2v;
                    i1s[row * 2 + wn] = biI;
                }
            }
        __syncthreads();

        // ---- merge halves + running (one thread per point) ----
        if (tid < 128) {
            float a1 = v1s[tid * 2], a2 = v2s[tid * 2]; int ai = i1s[tid * 2];
            float c1 = v1s[tid * 2 + 1], c2v = v2s[tid * 2 + 1]; int ci = i1s[tid * 2 + 1];
            float m2 = fminf(fminf(a2, c2v), fmaxf(a1, c1));
            float m1; int mi;
            if (c1 < a1) { m1 = c1; mi = ci; } else { m1 = a1; mi = ai; }
            float r1 = runv[tid], r2 = runv2[tid]; int riI = runi[tid];
            float nn2 = fminf(fminf(m2, r2), fmaxf(m1, r1));
            if (m1 < r1) { runv[tid] = m1; runi[tid] = mi; }
            runv2[tid] = nn2;
        }
    }
    __syncthreads();

    // ---- final epilogue ----
    if (tid < 128) {
        int k = runi[tid];
        out[OFF_IDX + n0 + tid] = (float)k;
        atomicAdd(&g_enc[k], 1.0f);
        if (runv2[tid] - runv[tid] < 4e-3f) {
            int fp = atomicAdd(&g_nflag, 1);
            g_flagged[fp] = n0 + tid;
        }
    }
    __syncthreads();

    float lsum = 0.0f;
    float* outq = out + OFF_Q + (size_t)bimg * CHW + p0;
#pragma unroll 4
    for (int r = 0; r < 32; ++r) {
        int e = tid + 256 * r;
        int c = e >> 7;
        int m = e & 127;
        int k = runi[m];
        float xv = xb[c * HW + m];
        float ev = E[c * NCODE + k];
        float diff = ev - xv;
        outq[c * HW + m] = xv + diff;
        lsum = fmaf(diff, diff, lsum);
        atomicAdd(&g_dw[c * NCODE + k], xv);
    }

    red[tid] = lsum;
    __syncthreads();
    for (int s = 128; s > 0; s >>= 1) {
        if (tid < s) red[tid] += red[tid + s];
        __syncthreads();
    }
    if (tid == 0) atomicAdd(&g_loss, red[0]);
}

// ---------------------------------------------------------------------------
// Kernel 3: exact-fp32 rescue of margin-flagged points
// ---------------------------------------------------------------------------
__global__ void vq_rescue(const float* __restrict__ x, const float* __restrict__ E,
                          float* __restrict__ out) {
    __shared__ float xs[64];
    __shared__ float bv[256];
    __shared__ int   bidx[256];
    const int tid = threadIdx.x;
    const int nf = g_nflag;

    for (int it = blockIdx.x; it < nf; it += gridDim.x) {
        int p = g_flagged[it];
        int bimg = p >> 12;
        int off = p & 4095;
        if (tid < 64) xs[tid] = x[(size_t)bimg * CHW + tid * HW + off];
        __syncthreads();

        float best = 3.4e38f; int kb = 0;
        for (int k = tid; k < NCODE; k += 256) {
            float dot = 0.0f;
#pragma unroll
            for (int c = 0; c < 64; ++c) dot = fmaf(xs[c], E[c * NCODE + k], dot);
            float sc = fmaf(-2.0f, dot, g_e2[k]);
            if (sc < best) { best = sc; kb = k; }
        }
        bv[tid] = best; bidx[tid] = kb;
        __syncthreads();
        for (int s = 128; s > 0; s >>= 1) {
            if (tid < s) {
                if (bv[tid + s] < bv[tid] ||
                    (bv[tid + s] == bv[tid] && bidx[tid + s] < bidx[tid])) {
                    bv[tid] = bv[tid + s]; bidx[tid] = bidx[tid + s];
                }
            }
            __syncthreads();
        }
        int kn = bidx[0];
        int ko = (int)out[OFF_IDX + p];
        __syncthreads();
        if (kn != ko) {
            if (tid == 0) {
                out[OFF_IDX + p] = (float)kn;
                atomicAdd(&g_enc[ko], -1.0f);
                atomicAdd(&g_enc[kn], 1.0f);
            }
            float ld = 0.0f;
            if (tid < 64) {
                int c = tid;
                float xv = xs[c];
                atomicAdd(&g_dw[c * NCODE + ko], -xv);
                atomicAdd(&g_dw[c * NCODE + kn], xv);
                float eo = E[c * NCODE + ko];
                float en = E[c * NCODE + kn];
                float dold = eo - xv, dnew = en - xv;
                out[OFF_Q + (size_t)bimg * CHW + c * HW + off] = xv + dnew;
                ld = dnew * dnew - dold * dold;
            }
            bv[tid] = ld;
            __syncthreads();
            for (int s = 128; s > 0; s >>= 1) {
                if (tid < s) bv[tid] += bv[tid + s];
                __syncthreads();
            }
            if (tid == 0) atomicAdd(&g_loss, bv[0]);
        }
        __syncthreads();
    }
}

// ---------------------------------------------------------------------------
// Kernel 4: EMA finalize + loss
// ---------------------------------------------------------------------------
__global__ void vq_fin(const float* __restrict__ cs_in,
                       const float* __restrict__ ea_in,
                       float* __restrict__ out) {
    __shared__ float red[1024];
    int k = threadIdx.x;
    float ncs = cs_in[k] * 0.99f + 0.01f * g_enc[k];
    red[k] = ncs;
    __syncthreads();
    for (int s = 512; s > 0; s >>= 1) {
        if (k < s) red[k] += red[k + s];
        __syncthreads();
    }
    float n = red[0];
    out[OFF_CS + k] = ncs;
    float cs = (ncs + 1e-5f) / (n + 1024.0f * 1e-5f) * n;
#pragma unroll
    for (int d = 0; d < DIM; ++d) {
        int idx = d * NCODE + k;
        float nea = ea_in[idx] * 0.99f + 0.01f * g_dw[idx];
        out[OFF_EA + idx] = nea;
        out[OFF_EMB + idx] = nea / cs;
    }
    if (k == 0) out[OFF_LOSS] = 0.25f * g_loss * (1.0f / (float)TOTAL_Q);
}

// ---------------------------------------------------------------------------
extern "C" void kernel_launch(void* const* d_in, const int* in_sizes, int n_in,
                              void* d_out, int out_size) {
    const float* x  = (const float*)d_in[0];
    const float* E  = (const float*)d_in[1];
    const float* cs = (const float*)d_in[2];
    const float* ea = (const float*)d_in[3];
    float* out = (float*)d_out;

    cudaFuncSetAttribute(vq_main, cudaFuncAttributeMaxDynamicSharedMemorySize, SM_TOTAL);

    vq_init<<<256, 256>>>(E);
    vq_main<<<NPTS / 128, 256, SM_TOTAL>>>(x, E, out);
    vq_rescue<<<128, 256>>>(x, E, out);
    vq_fin<<<1, 1024>>>(cs, ea, out);
}